// round 17
// baseline (speedup 1.0000x reference)
#include <cuda_runtime.h>
#include <cuda_fp16.h>
#include <math.h>
#include <stdint.h>

// Problem constants
#define Bc 32
#define Sc 512
#define Hc 768
#define Lc 6
#define NHc 12
#define FFc 3072
#define Tc 7
#define DHc 64
#define BSc (Bc*Sc)          // 16384
#define QKVN (3*Hc)          // 2304

// ---------------- scratch buffers (compact token layout) -------------------------
__device__ float   g_x  [(size_t)BSc*Hc];
__device__ __half  g_xb [(size_t)BSc*Hc];
__device__ float   g_y  [(size_t)BSc*Hc];
__device__ __half  g_qkv[(size_t)BSc*QKVN];
__device__ __half  g_ctx[(size_t)BSc*Hc];
__device__ __half  g_h  [(size_t)BSc*FFc];
__device__ __half  g_wb [(size_t)(4*Lc*Hc*Hc + 2*Lc*Hc*FFc)];
__device__ float   g_bqkv[(size_t)Lc*QKVN];
__device__ float   g_em [(size_t)BSc*Tc];
__device__ int     g_len[Bc];
__device__ int     g_off[Bc + 1];
__device__ float   g_num[Bc];
__device__ float   g_den[Bc];

// ---------------- PTX helpers ---------------------------------------------------
__device__ __forceinline__ unsigned smem_u32(const void* p) {
    return (unsigned)__cvta_generic_to_shared(p);
}
__device__ __forceinline__ void cp16(unsigned saddr, const void* g) {
    asm volatile("cp.async.cg.shared.global [%0], [%1], 16;\n" :: "r"(saddr), "l"(g));
}
__device__ __forceinline__ void cp_commit() {
    asm volatile("cp.async.commit_group;\n");
}
template<int N>
__device__ __forceinline__ void cp_wait() {
    asm volatile("cp.async.wait_group %0;\n" :: "n"(N));
}
__device__ __forceinline__ void ldsm_x4(unsigned r[4], unsigned addr) {
    asm volatile("ldmatrix.sync.aligned.m8n8.x4.shared.b16 {%0,%1,%2,%3}, [%4];\n"
        : "=r"(r[0]), "=r"(r[1]), "=r"(r[2]), "=r"(r[3]) : "r"(addr));
}
__device__ __forceinline__ void ldsm_x4_t(unsigned r[4], unsigned addr) {
    asm volatile("ldmatrix.sync.aligned.m8n8.x4.trans.shared.b16 {%0,%1,%2,%3}, [%4];\n"
        : "=r"(r[0]), "=r"(r[1]), "=r"(r[2]), "=r"(r[3]) : "r"(addr));
}
__device__ __forceinline__ void mma_h_f32(float c[4], const unsigned a[4], const unsigned b[2]) {
    asm volatile("mma.sync.aligned.m16n8k16.row.col.f32.f16.f16.f32 "
        "{%0,%1,%2,%3}, {%4,%5,%6,%7}, {%8,%9}, {%0,%1,%2,%3};\n"
        : "+f"(c[0]), "+f"(c[1]), "+f"(c[2]), "+f"(c[3])
        : "r"(a[0]), "r"(a[1]), "r"(a[2]), "r"(a[3]), "r"(b[0]), "r"(b[1]));
}
__device__ __forceinline__ void mma_h_f16(unsigned c[2], const unsigned a[4], const unsigned b[2]) {
    asm volatile("mma.sync.aligned.m16n8k16.row.col.f16.f16.f16.f16 "
        "{%0,%1}, {%2,%3,%4,%5}, {%6,%7}, {%0,%1};\n"
        : "+r"(c[0]), "+r"(c[1])
        : "r"(a[0]), "r"(a[1]), "r"(a[2]), "r"(a[3]), "r"(b[0]), "r"(b[1]));
}
__device__ __forceinline__ unsigned packh2(float a, float b) {
    __half2 t = __floats2half2_rn(a, b);
    return *(unsigned*)&t;
}

__device__ __forceinline__ float gelu_exact(float x) {
    return 0.5f * x * (1.0f + erff(x * 0.70710678118654752f));
}

// ---------------- lengths + prefix offsets ---------------------------------------
__global__ void len_kernel(const int* __restrict__ amask,
                           int* __restrict__ lens, int* __restrict__ off)
{
    __shared__ int sl[Bc];
    int warp = threadIdx.x >> 5, lane = threadIdx.x & 31;
    for (int b = warp; b < Bc; b += 8) {
        int s = 0;
        for (int j = lane; j < Sc; j += 32) s += amask[(size_t)b*Sc + j];
        #pragma unroll
        for (int o = 16; o > 0; o >>= 1) s += __shfl_xor_sync(0xffffffffu, s, o);
        if (lane == 0) { lens[b] = s; sl[b] = s; }
    }
    __syncthreads();
    if (threadIdx.x == 0) {
        int acc = 0;
        for (int b = 0; b < Bc; b++) { off[b] = acc; acc += sl[b]; }
        off[Bc] = acc;
    }
}

// ---------------- fp32 -> f16 / pack helpers ------------------------------------
__global__ void f2h_kernel(const float* __restrict__ in, __half* __restrict__ out, int n)
{
    int stride = gridDim.x * blockDim.x * 4;
    for (int i = (blockIdx.x*blockDim.x + threadIdx.x)*4; i < n; i += stride) {
        float4 v = *(const float4*)(in + i);
        __half2* o = (__half2*)(out + i);
        o[0] = __floats2half2_rn(v.x, v.y);
        o[1] = __floats2half2_rn(v.z, v.w);
    }
}

// div-free QKV weight pack: one block per (l, k) row
__global__ void pack_qkv_w(const float* __restrict__ qw, const float* __restrict__ kw,
                           const float* __restrict__ vw, __half* __restrict__ out)
{
    int row = blockIdx.x;                       // l*Hc + k, 0..Lc*Hc-1
    size_t srow = (size_t)row * Hc;
    __half* orow = out + (size_t)row * QKVN;
    int tid = threadIdx.x;
    #pragma unroll
    for (int c = 0; c < 3; c++) {
        int col = tid + 256*c;
        orow[col]          = __float2half(qw[srow + col]);
        orow[Hc + col]     = __float2half(kw[srow + col]);
        orow[2*Hc + col]   = __float2half(vw[srow + col]);
    }
}

__global__ void pack_qkv_b(const float* __restrict__ qb, const float* __restrict__ kb,
                           const float* __restrict__ vb, float* __restrict__ out)
{
    int i = blockIdx.x*blockDim.x + threadIdx.x;
    if (i >= Lc*QKVN) return;
    int l = i / QKVN, n = i % QKVN;
    float v;
    if (n < Hc)        v = qb[l*Hc + n];
    else if (n < 2*Hc) v = kb[l*Hc + n - Hc];
    else               v = vb[l*Hc + n - 2*Hc];
    out[i] = v;
}

// ---------------- warp-per-token embedding + LN (compact rows) -------------------
__global__ __launch_bounds__(256) void embed_ln_warp(
    const float* __restrict__ wemb, const float* __restrict__ pemb,
    const float* __restrict__ g, const float* __restrict__ bt,
    const int* __restrict__ ids, const int* __restrict__ lens,
    const int* __restrict__ off,
    float* __restrict__ x, __half* __restrict__ xb)
{
    int warp = threadIdx.x >> 5, lane = threadIdx.x & 31;
    int token = blockIdx.x*8 + warp;
    int b = token >> 9, s = token & (Sc-1);
    if (s >= lens[b]) return;
    size_t crow = (size_t)(off[b] + s);
    int id = ids[token];
    const float4* w4 = (const float4*)(wemb + (size_t)id*Hc);
    const float4* p4 = (const float4*)(pemb + (size_t)s*Hc);
    float4 v[6];
    float sm = 0.f, s2 = 0.f;
    #pragma unroll
    for (int i = 0; i < 6; i++) {
        float4 a = w4[lane + 32*i], p = p4[lane + 32*i];
        v[i].x = a.x + p.x; v[i].y = a.y + p.y;
        v[i].z = a.z + p.z; v[i].w = a.w + p.w;
        sm += v[i].x + v[i].y + v[i].z + v[i].w;
        s2 += v[i].x*v[i].x + v[i].y*v[i].y + v[i].z*v[i].z + v[i].w*v[i].w;
    }
    #pragma unroll
    for (int o = 16; o > 0; o >>= 1) {
        sm += __shfl_xor_sync(0xffffffffu, sm, o);
        s2 += __shfl_xor_sync(0xffffffffu, s2, o);
    }
    float mean = sm * (1.0f/Hc);
    float inv  = rsqrtf(s2 * (1.0f/Hc) - mean*mean + 1e-12f);
    const float4* g4 = (const float4*)g;
    const float4* b4 = (const float4*)bt;
    float4* xr = (float4*)(x + crow*Hc);
    #pragma unroll
    for (int i = 0; i < 6; i++) {
        float4 gg = g4[lane + 32*i], bb = b4[lane + 32*i];
        float4 o;
        o.x = (v[i].x - mean)*inv*gg.x + bb.x;
        o.y = (v[i].y - mean)*inv*gg.y + bb.y;
        o.z = (v[i].z - mean)*inv*gg.z + bb.z;
        o.w = (v[i].w - mean)*inv*gg.w + bb.w;
        xr[lane + 32*i] = o;
        *(uint2*)&xb[crow*Hc + (lane + 32*i)*4] =
            make_uint2(packh2(o.x, o.y), packh2(o.z, o.w));
    }
}

// ---------------- warp-per-token LN (compact rows) --------------------------------
__global__ __launch_bounds__(256) void ln_warp(
    const float* __restrict__ y, const float* __restrict__ g,
    const float* __restrict__ bt, const int* __restrict__ off,
    float* __restrict__ x, __half* __restrict__ xb)
{
    int warp = threadIdx.x >> 5, lane = threadIdx.x & 31;
    int token = blockIdx.x*8 + warp;
    if (token >= off[Bc]) return;
    const float4* yr = (const float4*)(y + (size_t)token*Hc);
    float4 v[6];
    float s = 0.f, s2 = 0.f;
    #pragma unroll
    for (int i = 0; i < 6; i++) {
        v[i] = yr[lane + 32*i];
        s  += v[i].x + v[i].y + v[i].z + v[i].w;
        s2 += v[i].x*v[i].x + v[i].y*v[i].y + v[i].z*v[i].z + v[i].w*v[i].w;
    }
    #pragma unroll
    for (int o = 16; o > 0; o >>= 1) {
        s  += __shfl_xor_sync(0xffffffffu, s,  o);
        s2 += __shfl_xor_sync(0xffffffffu, s2, o);
    }
    float mean = s * (1.0f/Hc);
    float inv  = rsqrtf(s2 * (1.0f/Hc) - mean*mean + 1e-12f);
    const float4* g4 = (const float4*)g;
    const float4* b4 = (const float4*)bt;
    float4* xr = (float4*)(x + (size_t)token*Hc);
    #pragma unroll
    for (int i = 0; i < 6; i++) {
        float4 gg = g4[lane + 32*i], bb = b4[lane + 32*i];
        float4 o;
        o.x = (v[i].x - mean)*inv*gg.x + bb.x;
        o.y = (v[i].y - mean)*inv*gg.y + bb.y;
        o.z = (v[i].z - mean)*inv*gg.z + bb.z;
        o.w = (v[i].w - mean)*inv*gg.w + bb.w;
        xr[lane + 32*i] = o;
        *(uint2*)&xb[(size_t)token*Hc + (lane + 32*i)*4] =
            make_uint2(packh2(o.x, o.y), packh2(o.z, o.w));
    }
}

// ---------------- f16 GEMM: CTA 128x256, warp 64x64, BK64, 3 stages, frag dbuf ---
#define LDA_S 72
#define LDB_S 264
#define STAGES 3
#define A_ST (128*LDA_S)
#define B_ST (64*LDB_S)
#define GEMM_SMEM (STAGES*(A_ST + B_ST)*2)   // 156672

__global__ __launch_bounds__(256) void gemm_mma(
    const __half* __restrict__ A, int lda,
    const __half* __restrict__ W, int ldb,
    const float* __restrict__ bias,
    const float* __restrict__ resid,
    const int* __restrict__ off,
    float* __restrict__ outf, __half* __restrict__ outb, int ldc,
    int K, int act)
{
    const int m0 = blockIdx.y * 128, n0 = blockIdx.x * 256;
    if (m0 >= off[Bc]) return;

    extern __shared__ char smx[];
    __half* As = (__half*)smx;
    __half* Bs = As + STAGES*A_ST;
    const int tid = threadIdx.x;
    const int lane = tid & 31, wid = tid >> 5;
    const int warp_m = wid & 1, warp_n = wid >> 1;   // 2 x 4, warp tile 64x64
    const int ktiles = K >> 6;

    unsigned acc[4][8][2];
    #pragma unroll
    for (int i = 0; i < 4; i++)
        #pragma unroll
        for (int j = 0; j < 8; j++) { acc[i][j][0] = 0u; acc[i][j][1] = 0u; }

    auto issue = [&](int stage, int kt) {
        __half* as = As + stage*A_ST;
        __half* bs = Bs + stage*B_ST;
        #pragma unroll
        for (int j = 0; j < 4; j++) {          // A: 128x64 = 1024 cp16
            int lin = tid + 256*j;
            int r = lin >> 3, c = (lin & 7) * 8;
            cp16(smem_u32(as + r*LDA_S + c), A + (size_t)(m0 + r)*lda + kt*64 + c);
        }
        #pragma unroll
        for (int j = 0; j < 8; j++) {          // B: 64x256 = 2048 cp16
            int lin = tid + 256*j;
            int r = lin >> 5, c = (lin & 31) * 8;
            cp16(smem_u32(bs + r*LDB_S + c), W + (size_t)(kt*64 + r)*ldb + n0 + c);
        }
    };

    #pragma unroll
    for (int s = 0; s < STAGES-1; s++) {
        if (s < ktiles) issue(s, s);
        cp_commit();
    }

    unsigned af[2][4][4];
    unsigned bfr[2][8][2];

    #define LOAD_FRAGS(buf, kkv) do { \
        _Pragma("unroll") \
        for (int mt = 0; mt < 4; mt++) { \
            int row = warp_m*64 + mt*16 + (lane & 15); \
            int col = (kkv)*16 + (lane >> 4) * 8; \
            ldsm_x4(af[buf][mt], asb + (row*LDA_S + col)*2); \
        } \
        _Pragma("unroll") \
        for (int nt2 = 0; nt2 < 4; nt2++) { \
            int row = (kkv)*16 + (lane & 15); \
            int col = warp_n*64 + nt2*16 + (lane >> 4) * 8; \
            unsigned rr[4]; \
            ldsm_x4_t(rr, bsb + (row*LDB_S + col)*2); \
            bfr[buf][nt2*2][0]   = rr[0]; bfr[buf][nt2*2][1]   = rr[1]; \
            bfr[buf][nt2*2+1][0] = rr[2]; bfr[buf][nt2*2+1][1] = rr[3]; \
        } \
    } while (0)

    for (int kt = 0; kt < ktiles; kt++) {
        cp_wait<STAGES-2>();
        __syncthreads();
        if (kt + STAGES-1 < ktiles) issue((kt + STAGES-1) % STAGES, kt + STAGES-1);
        cp_commit();

        int stage = kt % STAGES;
        const unsigned asb = smem_u32(As + stage*A_ST);
        const unsigned bsb = smem_u32(Bs + stage*B_ST);

        LOAD_FRAGS(0, 0);
        #pragma unroll
        for (int kk = 0; kk < 4; kk++) {
            int cur = kk & 1;
            if (kk < 3) LOAD_FRAGS(cur ^ 1, kk + 1);
            #pragma unroll
            for (int mt = 0; mt < 4; mt++)
                #pragma unroll
                for (int nt = 0; nt < 8; nt++)
                    mma_h_f16(acc[mt][nt], af[cur][mt], bfr[cur][nt]);
        }
    }
    #undef LOAD_FRAGS

    int orow = m0 + warp_m*64, ocol = n0 + warp_n*64;
    #pragma unroll
    for (int mt = 0; mt < 4; mt++) {
        int r = orow + mt*16 + (lane >> 2);
        #pragma unroll
        for (int nt = 0; nt < 8; nt++) {
            int c = ocol + nt*8 + (lane & 3)*2;
            float2 lo = __half22float2(*(__half2*)&acc[mt][nt][0]);
            float2 hi = __half22float2(*(__half2*)&acc[mt][nt][1]);
            float b0 = bias[c], b1 = bias[c+1];
            float v00 = lo.x + b0, v01 = lo.y + b1;
            float v10 = hi.x + b0, v11 = hi.y + b1;
            if (act) {
                v00 = gelu_exact(v00); v01 = gelu_exact(v01);
                v10 = gelu_exact(v10); v11 = gelu_exact(v11);
            }
            if (resid) {
                v00 += resid[(size_t)r*ldc + c];
                v01 += resid[(size_t)r*ldc + c + 1];
                v10 += resid[(size_t)(r+8)*ldc + c];
                v11 += resid[(size_t)(r+8)*ldc + c + 1];
            }
            if (outf) {
                *(float2*)&outf[(size_t)r*ldc + c]     = make_float2(v00, v01);
                *(float2*)&outf[(size_t)(r+8)*ldc + c] = make_float2(v10, v11);
            } else {
                *(__half2*)&outb[(size_t)r*ldc + c]     = __floats2half2_rn(v00, v01);
                *(__half2*)&outb[(size_t)(r+8)*ldc + c] = __floats2half2_rn(v10, v11);
            }
        }
    }
}

// ---------------- flash attention (compact layout, guarded writes) ---------------
#define FK_CH (64*72)
#define FL_Q_OFF   0
#define FL_K_OFF   18432
#define FL_V_OFF   (18432 + 18432)
#define FL_MV_OFF  (18432 + 18432 + 18432)
#define FLASH_SMEM (18432 + 18432 + 18432 + 2048)   // 57344

__global__ __launch_bounds__(256, 2) void flash_attn(
    const __half* __restrict__ qkv,
    const int* __restrict__ lens,
    const int* __restrict__ off,
    __half* __restrict__ ctx)
{
    const int bh = blockIdx.y, b = bh / NHc, h = bh % NHc;
    const int q0 = blockIdx.x * 128;
    const int len = lens[b];
    if (q0 >= len) return;
    const int base = off[b];

    extern __shared__ char smx[];
    __half* Qs = (__half*)(smx + FL_Q_OFF);
    __half* Ks = (__half*)(smx + FL_K_OFF);
    __half* Vs = (__half*)(smx + FL_V_OFF);
    float* maskv = (float*)(smx + FL_MV_OFF);

    const int tid = threadIdx.x, lane = tid & 31, wid = tid >> 5;
    const size_t rs = QKVN;
    const __half* kg = qkv + ((size_t)base)*rs + Hc + h*DHc;
    const __half* vg = qkv + ((size_t)base)*rs + 2*Hc + h*DHc;
    const __half* qg = qkv + ((size_t)(base + q0))*rs + h*DHc;

    const int lr = tid >> 2, lc2 = (tid & 3) * 16;
    auto loadKV = [&](int buf, int ch) {
        const __half* ks = kg + (size_t)(ch*64)*rs;
        const __half* vs = vg + (size_t)(ch*64)*rs;
        cp16(smem_u32(&Ks[buf*FK_CH + lr*72 + lc2]),      ks + (size_t)lr*rs + lc2);
        cp16(smem_u32(&Ks[buf*FK_CH + lr*72 + lc2 + 8]),  ks + (size_t)lr*rs + lc2 + 8);
        cp16(smem_u32(&Vs[buf*FK_CH + lr*72 + lc2]),      vs + (size_t)lr*rs + lc2);
        cp16(smem_u32(&Vs[buf*FK_CH + lr*72 + lc2 + 8]),  vs + (size_t)lr*rs + lc2 + 8);
    };

    {
        #pragma unroll
        for (int i = 0; i < 4; i++) {
            int lin = tid + 256*i;
            int r = lin >> 3, c = (lin & 7) * 8;
            cp16(smem_u32(&Qs[r*72 + c]), qg + (size_t)r*rs + c);
        }
        for (int j = tid; j < Sc; j += 256)
            maskv[j] = (j < len) ? 0.f : -1e30f;
        loadKV(0, 0);
    }
    cp_commit();
    cp_wait<0>();
    __syncthreads();

    const int nch = (len + 63) >> 6;

    const unsigned qsb = smem_u32(Qs);
    const unsigned ksb = smem_u32(Ks), vsb = smem_u32(Vs);

    unsigned aQ[4][4];
    #pragma unroll
    for (int kk = 0; kk < 4; kk++) {
        int row = wid*16 + (lane & 15);
        int col = kk*16 + (lane >> 4) * 8;
        ldsm_x4(aQ[kk], qsb + (row*72 + col)*2);
    }

    float m_s[2] = {-3.4e38f, -3.4e38f};
    float l_s[2] = {0.f, 0.f};
    float oacc[8][4];
    #pragma unroll
    for (int nt = 0; nt < 8; nt++)
        #pragma unroll
        for (int e = 0; e < 4; e++) oacc[nt][e] = 0.f;

    for (int ch = 0; ch < nch; ch++) {
        const int buf = ch & 1;
        const unsigned kcb = ksb + buf*FK_CH*2;
        const unsigned vcb = vsb + buf*FK_CH*2;
        const int j0 = ch * 64;

        if (ch + 1 < nch) loadKV(buf ^ 1, ch + 1);
        cp_commit();

        float sc[8][4];
        #pragma unroll
        for (int nt = 0; nt < 8; nt++)
            #pragma unroll
            for (int e = 0; e < 4; e++) sc[nt][e] = 0.f;

        #pragma unroll
        for (int kk = 0; kk < 4; kk++) {
            unsigned bK[8][2];
            #pragma unroll
            for (int nt2 = 0; nt2 < 4; nt2++) {
                int row = nt2*16 + (lane & 7) + ((lane >> 4) << 3);
                int col = kk*16 + ((lane >> 3) & 1) * 8;
                unsigned r[4];
                ldsm_x4(r, kcb + (row*72 + col)*2);
                bK[nt2*2][0] = r[0]; bK[nt2*2][1] = r[1];
                bK[nt2*2+1][0] = r[2]; bK[nt2*2+1][1] = r[3];
            }
            #pragma unroll
            for (int nt = 0; nt < 8; nt++)
                mma_h_f32(sc[nt], aQ[kk], bK[nt]);
        }

        #pragma unroll
        for (int nt = 0; nt < 8; nt++) {
            int cb = j0 + nt*8 + (lane & 3)*2;
            float m0v = maskv[cb], m1v = maskv[cb+1];
            sc[nt][0] = sc[nt][0]*0.125f + m0v;
            sc[nt][1] = sc[nt][1]*0.125f + m1v;
            sc[nt][2] = sc[nt][2]*0.125f + m0v;
            sc[nt][3] = sc[nt][3]*0.125f + m1v;
        }

        float cmax[2] = {-3.4e38f, -3.4e38f};
        #pragma unroll
        for (int nt = 0; nt < 8; nt++) {
            cmax[0] = fmaxf(cmax[0], fmaxf(sc[nt][0], sc[nt][1]));
            cmax[1] = fmaxf(cmax[1], fmaxf(sc[nt][2], sc[nt][3]));
        }
        #pragma unroll
        for (int g = 0; g < 2; g++) {
            cmax[g] = fmaxf(cmax[g], __shfl_xor_sync(0xffffffffu, cmax[g], 1));
            cmax[g] = fmaxf(cmax[g], __shfl_xor_sync(0xffffffffu, cmax[g], 2));
        }

        float mnew[2], scale[2];
        #pragma unroll
        for (int g = 0; g < 2; g++) {
            mnew[g]  = fmaxf(m_s[g], cmax[g]);
            scale[g] = exp2f((m_s[g] - mnew[g]) * 1.4426950408889634f);
            m_s[g]   = mnew[g];
        }

        float csum[2] = {0.f, 0.f};
        unsigned aP[4][4];
        #pragma unroll
        for (int kb = 0; kb < 4; kb++) {
            float p0a = exp2f((sc[2*kb][0]   - mnew[0]) * 1.4426950408889634f);
            float p0b = exp2f((sc[2*kb][1]   - mnew[0]) * 1.4426950408889634f);
            float p1a = exp2f((sc[2*kb][2]   - mnew[1]) * 1.4426950408889634f);
            float p1b = exp2f((sc[2*kb][3]   - mnew[1]) * 1.4426950408889634f);
            float q0a = exp2f((sc[2*kb+1][0] - mnew[0]) * 1.4426950408889634f);
            float q0b = exp2f((sc[2*kb+1][1] - mnew[0]) * 1.4426950408889634f);
            float q1a = exp2f((sc[2*kb+1][2] - mnew[1]) * 1.4426950408889634f);
            float q1b = exp2f((sc[2*kb+1][3] - mnew[1]) * 1.4426950408889634f);
            csum[0] += p0a + p0b + q0a + q0b;
            csum[1] += p1a + p1b + q1a + q1b;
            aP[kb][0] = packh2(p0a, p0b);
            aP[kb][1] = packh2(p1a, p1b);
            aP[kb][2] = packh2(q0a, q0b);
            aP[kb][3] = packh2(q1a, q1b);
        }
        #pragma unroll
        for (int g = 0; g < 2; g++) {
            csum[g] += __shfl_xor_sync(0xffffffffu, csum[g], 1);
            csum[g] += __shfl_xor_sync(0xffffffffu, csum[g], 2);
            l_s[g] = l_s[g]*scale[g] + csum[g];
        }

        #pragma unroll
        for (int nt = 0; nt < 8; nt++) {
            oacc[nt][0] *= scale[0];
            oacc[nt][1] *= scale[0];
            oacc[nt][2] *= scale[1];
            oacc[nt][3] *= scale[1];
        }
        #pragma unroll
        for (int kb = 0; kb < 4; kb++) {
            unsigned bv[8][2];
            #pragma unroll
            for (int nt2 = 0; nt2 < 4; nt2++) {
                int row = kb*16 + (lane & 15);
                int col = nt2*16 + (lane >> 4) * 8;
                unsigned r[4];
                ldsm_x4_t(r, vcb + (row*72 + col)*2);
                bv[nt2*2][0] = r[0]; bv[nt2*2][1] = r[1];
                bv[nt2*2+1][0] = r[2]; bv[nt2*2+1][1] = r[3];
            }
            #pragma unroll
            for (int nt = 0; nt < 8; nt++)
                mma_h_f32(oacc[nt], aP[kb], bv[nt]);
        }

        if (ch + 1 < nch) {
            cp_wait<0>();
            __syncthreads();
        }
    }

    float inv0 = 1.0f / l_s[0], inv1 = 1.0f / l_s[1];
    int r0 = wid*16 + (lane >> 2);
    if (q0 + r0 < len) {
        __half2* d0 = (__half2*)&ctx[((size_t)(base + q0 + r0))*Hc + h*DHc + (lane & 3)*2];
        #pragma unroll
        for (int nt = 0; nt < 8; nt++)
            d0[nt*4] = __floats2half2_rn(oacc[nt][0]*inv0, oacc[nt][1]*inv0);
    }
    if (q0 + r0 + 8 < len) {
        __half2* d1 = (__half2*)&ctx[((size_t)(base + q0 + r0 + 8))*Hc + h*DHc + (lane & 3)*2];
        #pragma unroll
        for (int nt = 0; nt < 8; nt++)
            d1[nt*4] = __floats2half2_rn(oacc[nt][2]*inv1, oacc[nt][3]*inv1);
    }
}

// ---------------- emissions: compact x -> original-layout em ---------------------
__global__ void emissions_kernel(const float* __restrict__ x,
                                 const float* __restrict__ cw,
                                 const float* __restrict__ cb,
                                 const int* __restrict__ lens,
                                 const int* __restrict__ off,
                                 float* __restrict__ em)
{
    int token = blockIdx.x;
    int b = token >> 9, s = token & (Sc-1);
    if (s >= lens[b]) return;
    int w = threadIdx.x >> 5, lane = threadIdx.x & 31;
    const float* xr = x + (size_t)(off[b] + s)*Hc;
    float sum = 0.f;
    for (int c = lane; c < Hc; c += 32) sum += xr[c] * cw[(size_t)c*Tc + w];
    #pragma unroll
    for (int o = 16; o > 0; o >>= 1) sum += __shfl_down_sync(0xffffffffu, sum, o);
    if (lane == 0) em[(size_t)token*Tc + w] = sum + cb[w];
}

// ---------------- CRF ----------------------------------------------------------
__device__ __forceinline__ float crf_block_reduce(float v, float* sbuf) {
    int tid = threadIdx.x;
    int lane = tid & 31, warp = tid >> 5;
    int nw = (blockDim.x + 31) >> 5;
    #pragma unroll
    for (int o = 16; o > 0; o >>= 1) v += __shfl_xor_sync(0xffffffffu, v, o);
    __syncthreads();
    if (lane == 0) sbuf[warp] = v;
    __syncthreads();
    if (warp == 0) {
        float w = (lane < nw) ? sbuf[lane] : 0.f;
        #pragma unroll
        for (int o = 16; o > 0; o >>= 1) w += __shfl_xor_sync(0xffffffffu, w, o);
        if (lane == 0) sbuf[0] = w;
    }
    __syncthreads();
    return sbuf[0];
}

__global__ void crf_kernel(const float* __restrict__ em,
                           const int*   __restrict__ labels,
                           const float* __restrict__ cstart,
                           const float* __restrict__ cend,
                           const float* __restrict__ ctrans,
                           float* __restrict__ num_out,
                           float* __restrict__ den_out)
{
    __shared__ float tr[Tc*Tc];
    __shared__ float sbuf[32];
    __shared__ int   s_len;
    int b = blockIdx.x, tid = threadIdx.x;
    const int* lab = labels + (size_t)b*Sc;
    const float* e = em + (size_t)b*Sc*Tc;
    if (tid < Tc*Tc) tr[tid] = ctrans[tid];
    __syncthreads();

    float cnt = 0.f, part = 0.f;
    for (int t = tid; t < Sc; t += blockDim.x) {
        bool m = (t == 0) || (lab[t] != -100);
        if (m) cnt += 1.f;
        if (t >= 1 && lab[t] != -100) {
            int cur = lab[t];
            int prv;
            if (t - 1 == 0) { prv = lab[0]; prv = prv < 0 ? 0 : (prv > Tc-1 ? Tc-1 : prv); }
            else            { prv = lab[t-1]; if (prv == -100) prv = 0; }
            part += tr[prv*Tc + cur] + e[(size_t)t*Tc + cur];
        }
    }
    float totc = crf_block_reduce(cnt, sbuf);
    float tot  = crf_block_reduce(part, sbuf);
    if (tid == 0) {
        int len = (int)(totc + 0.5f);
        s_len = len;
        int s0 = lab[0]; s0 = s0 < 0 ? 0 : (s0 > Tc-1 ? Tc-1 : s0);
        float num = cstart[s0] + e[s0] + tot;
        int send = len - 1;
        int sl;
        if (send == 0) sl = s0;
        else { sl = lab[send]; if (sl == -100) sl = 0; }
        num += cend[sl];
        num_out[b] = num;
    }
    __syncthreads();
    int len = s_len;

    if (tid < 32) {
        int j = tid;
        int jj = (j < Tc) ? j : 0;
        float a = cstart[jj] + e[jj];
        for (int t = 1; t < len; t++) {
            float ej = e[(size_t)t*Tc + jj];
            float av[Tc];
            float m = -3.4028235e+38f;
            #pragma unroll
            for (int i = 0; i < Tc; i++) {
                float ai = __shfl_sync(0xffffffffu, a, i);
                float vv = ai + tr[i*Tc + jj];
                av[i] = vv; m = fmaxf(m, vv);
            }
            float ss = 0.f;
            #pragma unroll
            for (int i = 0; i < Tc; i++) ss += expf(av[i] - m);
            float ne = m + logf(ss) + ej;
            a = (j < Tc) ? ne : a;
        }
        float fa = (j < Tc) ? a + cend[jj] : -3.4028235e+38f;
        float mm = fa;
        #pragma unroll
        for (int o = 16; o > 0; o >>= 1) mm = fmaxf(mm, __shfl_xor_sync(0xffffffffu, mm, o));
        float es = (j < Tc) ? expf(fa - mm) : 0.f;
        #pragma unroll
        for (int o = 16; o > 0; o >>= 1) es += __shfl_xor_sync(0xffffffffu, es, o);
        if (tid == 0) den_out[b] = mm + logf(es);
    }
}

// ---------------- final loss ----------------------------------------------------
__global__ void loss_kernel(const float* __restrict__ num,
                            const float* __restrict__ den,
                            float* __restrict__ out)
{
    int tid = threadIdx.x;
    float v = (tid < Bc) ? (num[tid] - den[tid]) : 0.f;
    #pragma unroll
    for (int o = 16; o > 0; o >>= 1) v += __shfl_down_sync(0xffffffffu, v, o);
    if (tid == 0) out[0] = -v / (float)Bc;
}

// ---------------- host launcher --------------------------------------------------
extern "C" void kernel_launch(void* const* d_in, const int* in_sizes, int n_in,
                              void* d_out, int out_size)
{
    const float* word_emb = (const float*)d_in[0];
    const float* pos_emb  = (const float*)d_in[1];
    const float* emb_ln_s = (const float*)d_in[2];
    const float* emb_ln_b = (const float*)d_in[3];
    const float* attn_qw  = (const float*)d_in[4];
    const float* attn_qb  = (const float*)d_in[5];
    const float* attn_kw  = (const float*)d_in[6];
    const float* attn_kb  = (const float*)d_in[7];
    const float* attn_vw  = (const float*)d_in[8];
    const float* attn_vb  = (const float*)d_in[9];
    const float* attn_ow  = (const float*)d_in[10];
    const float* attn_ob  = (const float*)d_in[11];
    const float* ln1_s    = (const float*)d_in[12];
    const float* ln1_b    = (const float*)d_in[13];
    const float* ffn_w1   = (const float*)d_in[14];
    const float* ffn_b1   = (const float*)d_in[15];
    const float* ffn_w2   = (const float*)d_in[16];
    const float* ffn_b2   = (const float*)d_in[17];
    const float* ln2_s    = (const float*)d_in[18];
    const float* ln2_b    = (const float*)d_in[19];
    const float* cls_w    = (const float*)d_in[20];
    const float* cls_b    = (const float*)d_in[21];
    const float* crf_start= (const float*)d_in[22];
    const float* crf_end  = (const float*)d_in[23];
    const float* crf_trans= (const float*)d_in[24];
    const int* input_ids  = (const int*)d_in[25];
    const int* amask      = (const int*)d_in[26];
    const int* labels     = (const int*)d_in[27];

    float *x, *y, *em, *nb, *db, *bqkv;
    int *lens, *off;
    __half *xb, *qkv, *ctx, *hb, *wb;
    cudaGetSymbolAddress((void**)&x,    g_x);
    cudaGetSymbolAddress((void**)&xb,   g_xb);
    cudaGetSymbolAddress((void**)&y,    g_y);
    cudaGetSymbolAddress((void**)&qkv,  g_qkv);
    cudaGetSymbolAddress((void**)&ctx,  g_ctx);
    cudaGetSymbolAddress((void**)&hb,   g_h);
    cudaGetSymbolAddress((void**)&wb,   g_wb);
    cudaGetSymbolAddress((void**)&bqkv, g_bqkv);
    cudaGetSymbolAddress((void**)&em,   g_em);
    cudaGetSymbolAddress((void**)&lens, g_len);
    cudaGetSymbolAddress((void**)&off,  g_off);
    cudaGetSymbolAddress((void**)&nb,   g_num);
    cudaGetSymbolAddress((void**)&db,   g_den);

    cudaFuncSetAttribute(gemm_mma,   cudaFuncAttributeMaxDynamicSharedMemorySize, GEMM_SMEM);
    cudaFuncSetAttribute(flash_attn, cudaFuncAttributeMaxDynamicSharedMemorySize, FLASH_SMEM);

    const size_t HH = (size_t)Lc*Hc*Hc;
    const size_t HF = (size_t)Lc*Hc*FFc;
    __half* wqkv = wb;
    __half* wo   = wb + 3*HH;
    __half* w1   = wb + 4*HH;
    __half* w2   = wb + 4*HH + HF;

    len_kernel<<<1, 256>>>(amask, lens, off);                                        // 0
    pack_qkv_w<<<Lc*Hc, 256>>>(attn_qw, attn_kw, attn_vw, wqkv);                     // 1
    pack_qkv_b<<<(Lc*QKVN + 255)/256, 256>>>(attn_qb, attn_kb, attn_vb, bqkv);       // 2
    embed_ln_warp<<<BSc/8, 256>>>(word_emb, pos_emb, emb_ln_s, emb_ln_b,
                                  input_ids, lens, off, x, xb);                      // 3

    dim3 gQKV(QKVN/256, BSc/128);   // 9 x 128
    dim3 gO(Hc/256, BSc/128);       // 3 x 128
    dim3 gF1(FFc/256, BSc/128);     // 12 x 128

    gemm_mma<<<gQKV, 256, GEMM_SMEM>>>(xb, Hc, wqkv, QKVN, bqkv, nullptr, off,
                                       nullptr, qkv, QKVN, Hc, 0);                   // 4

    f2h_kernel<<<2048, 256>>>(attn_ow, wo, (int)HH);                                 // 5
    f2h_kernel<<<4096, 256>>>(ffn_w1, w1, (int)HF);                                  // 6
    f2h_kernel<<<4096, 256>>>(ffn_w2, w2, (int)HF);                                  // 7

    for (int i = 0; i < Lc; i++) {
        size_t bOff = (size_t)i*Hc;
        if (i > 0) {
            gemm_mma<<<gQKV, 256, GEMM_SMEM>>>(xb, Hc, wqkv + (size_t)i*Hc*QKVN, QKVN,
                                               bqkv + (size_t)i*QKVN, nullptr, off,
                                               nullptr, qkv, QKVN, Hc, 0);
        }
        flash_attn<<<dim3(Sc/128, Bc*NHc), 256, FLASH_SMEM>>>(qkv, lens, off, ctx);

        gemm_mma<<<gO, 256, GEMM_SMEM>>>(ctx, Hc, wo + (size_t)i*Hc*Hc, Hc,
                                         attn_ob + bOff, x, off, y, nullptr, Hc, Hc, 0);
        ln_warp<<<BSc/8, 256>>>(y, ln1_s + bOff, ln1_b + bOff, off, x, xb);

        gemm_mma<<<gF1, 256, GEMM_SMEM>>>(xb, Hc, w1 + (size_t)i*Hc*FFc, FFc,
                                          ffn_b1 + (size_t)i*FFc, nullptr, off,
                                          nullptr, hb, FFc, Hc, 1);
        gemm_mma<<<gO, 256, GEMM_SMEM>>>(hb, FFc, w2 + (size_t)i*FFc*Hc, Hc,
                                         ffn_b2 + bOff, x, off, y, nullptr, Hc, FFc, 0);
        ln_warp<<<BSc/8, 256>>>(y, ln2_s + bOff, ln2_b + bOff, off, x, xb);
    }

    emissions_kernel<<<BSc, 224>>>(x, cls_w, cls_b, lens, off, em);
    crf_kernel<<<Bc, 256>>>(em, labels, crf_start, crf_end, crf_trans, nb, db);
    loss_kernel<<<1, 32>>>(nb, db, (float*)d_out);
}